// round 1
// baseline (speedup 1.0000x reference)
#include <cuda_runtime.h>
#include <math.h>

#define N_SEQ 2048
#define EMB   1024
#define KVE   256
#define HD    64
#define QH    16

// ---------------- scratch (device globals; no allocation) ----------------
__device__ float g_q[N_SEQ * EMB];     // scaled q projection (b n, E)
__device__ float g_k[N_SEQ * KVE];     // k projection
__device__ float g_v[N_SEQ * KVE];     // v projection
__device__ float g_attn[N_SEQ * EMB];  // attention output before LN

// =========================================================================
// Projection GEMM: C[n, m] = (X[n, :] . W[m, :] + bias[m]) * scale
// X: (2048, 1024) row-major, W: (M, 1024) row-major, C: (2048, M)
// 64x64 tile per block, BK=16, 256 threads, 4x4 micro-tile per thread.
// =========================================================================
__global__ __launch_bounds__(256) void proj_kernel(
    const float* __restrict__ X, const float* __restrict__ W,
    const float* __restrict__ bias, float* __restrict__ C,
    int M, float scale)
{
    __shared__ float Xs[16][65];
    __shared__ float Ws[16][65];

    const int tid = threadIdx.x;
    const int tx = tid & 15;
    const int ty = tid >> 4;
    const int n0 = blockIdx.y * 64;
    const int m0 = blockIdx.x * 64;

    float acc[4][4];
#pragma unroll
    for (int i = 0; i < 4; i++)
#pragma unroll
        for (int j = 0; j < 4; j++) acc[i][j] = 0.f;

    const int lr = tid >> 2;          // 0..63
    const int lc = (tid & 3) << 2;    // 0,4,8,12

    for (int k0 = 0; k0 < EMB; k0 += 16) {
        float4 xv = *(const float4*)(X + (size_t)(n0 + lr) * EMB + k0 + lc);
        float4 wv = *(const float4*)(W + (size_t)(m0 + lr) * EMB + k0 + lc);
        Xs[lc + 0][lr] = xv.x; Xs[lc + 1][lr] = xv.y;
        Xs[lc + 2][lr] = xv.z; Xs[lc + 3][lr] = xv.w;
        Ws[lc + 0][lr] = wv.x; Ws[lc + 1][lr] = wv.y;
        Ws[lc + 2][lr] = wv.z; Ws[lc + 3][lr] = wv.w;
        __syncthreads();
#pragma unroll
        for (int kk = 0; kk < 16; kk++) {
            float a[4], b[4];
#pragma unroll
            for (int i = 0; i < 4; i++) a[i] = Xs[kk][ty + 16 * i];
#pragma unroll
            for (int j = 0; j < 4; j++) b[j] = Ws[kk][tx + 16 * j];
#pragma unroll
            for (int i = 0; i < 4; i++)
#pragma unroll
                for (int j = 0; j < 4; j++)
                    acc[i][j] = fmaf(a[i], b[j], acc[i][j]);
        }
        __syncthreads();
    }

#pragma unroll
    for (int j = 0; j < 4; j++) {
        float bj = bias[m0 + tx + 16 * j];
#pragma unroll
        for (int i = 0; i < 4; i++) {
            C[(size_t)(n0 + ty + 16 * i) * M + m0 + tx + 16 * j] =
                (acc[i][j] + bj) * scale;
        }
    }
}

// =========================================================================
// Flash-style GQA attention, fp32, non-causal.
// Block = (query tile of 64 rows, one query head). 256 threads.
// Online softmax; P written transposed into the K smem buffer.
// Dynamic smem: Qts[64][65] + KPs[64][65] + Vs[64][64] = 49664 B
// =========================================================================
__global__ __launch_bounds__(256) void attn_kernel()
{
    extern __shared__ float sm[];
    float* Qts = sm;              // [64][65], d-major: Qts[d][row]
    float* KPs = sm + 64 * 65;    // [64][65], K: [d][s]; later P^T: [s][row]
    float* Vs  = sm + 2 * 64 * 65;// [64][64], row-major: Vs[s][d]

    const int tid  = threadIdx.x;
    const int tx   = tid & 15;
    const int ty   = tid >> 4;
    const int head = blockIdx.y;       // 0..15
    const int kvh  = head >> 2;        // GQA: group size 4
    const int m0   = blockIdx.x * 64;

    const float* Qb = g_q + (size_t)m0 * EMB + head * HD;
    const float* Kb = g_k + kvh * HD;
    const float* Vb = g_v + kvh * HD;

    // Load Q tile transposed (d-major). q already scaled by 1/8.
#pragma unroll
    for (int it = 0; it < 4; ++it) {
        int e = tid + it * 256;       // float4 index, 1024 total
        int r = e >> 4;               // 0..63 (query row)
        int c = (e & 15) << 2;        // 0..60 (dim)
        float4 v = *(const float4*)(Qb + (size_t)r * EMB + c);
        Qts[(c + 0) * 65 + r] = v.x;
        Qts[(c + 1) * 65 + r] = v.y;
        Qts[(c + 2) * 65 + r] = v.z;
        Qts[(c + 3) * 65 + r] = v.w;
    }

    float O[4][4];
    float mi[4], li[4];
#pragma unroll
    for (int i = 0; i < 4; i++) {
        mi[i] = -1e30f; li[i] = 0.f;
#pragma unroll
        for (int j = 0; j < 4; j++) O[i][j] = 0.f;
    }

    const float LOG2E = 1.4426950408889634f;

    for (int s0 = 0; s0 < N_SEQ; s0 += 64) {
        __syncthreads();  // prev PV reads done (and Q load visible on 1st iter)

        // Load K chunk transposed ([d][s]) and V chunk row-major ([s][d]).
#pragma unroll
        for (int it = 0; it < 4; ++it) {
            int e = tid + it * 256;
            int r = e >> 4;              // s within chunk
            int c = (e & 15) << 2;       // dim
            float4 kv = *(const float4*)(Kb + (size_t)(s0 + r) * KVE + c);
            KPs[(c + 0) * 65 + r] = kv.x;
            KPs[(c + 1) * 65 + r] = kv.y;
            KPs[(c + 2) * 65 + r] = kv.z;
            KPs[(c + 3) * 65 + r] = kv.w;
            float4 vv = *(const float4*)(Vb + (size_t)(s0 + r) * KVE + c);
            *(float4*)(Vs + r * 64 + c) = vv;
        }
        __syncthreads();

        // S = Q @ K^T  (64x64 tile)
        float s[4][4];
#pragma unroll
        for (int i = 0; i < 4; i++)
#pragma unroll
            for (int j = 0; j < 4; j++) s[i][j] = 0.f;
#pragma unroll 8
        for (int kk = 0; kk < 64; kk++) {
            float a[4], b[4];
#pragma unroll
            for (int i = 0; i < 4; i++) a[i] = Qts[kk * 65 + ty + 16 * i];
#pragma unroll
            for (int j = 0; j < 4; j++) b[j] = KPs[kk * 65 + tx + 16 * j];
#pragma unroll
            for (int i = 0; i < 4; i++)
#pragma unroll
                for (int j = 0; j < 4; j++)
                    s[i][j] = fmaf(a[i], b[j], s[i][j]);
        }

        // Online softmax. Row i lives on the 16 lanes sharing ty (a half-warp).
        float rmax[4], rsum[4], mn[4], csc[4];
#pragma unroll
        for (int i = 0; i < 4; i++) {
            rmax[i] = s[i][0];
#pragma unroll
            for (int j = 1; j < 4; j++) rmax[i] = fmaxf(rmax[i], s[i][j]);
        }
#pragma unroll
        for (int off = 8; off; off >>= 1)
#pragma unroll
            for (int i = 0; i < 4; i++)
                rmax[i] = fmaxf(rmax[i], __shfl_xor_sync(0xffffffffu, rmax[i], off));
#pragma unroll
        for (int i = 0; i < 4; i++) {
            mn[i]  = fmaxf(mi[i], rmax[i]);
            csc[i] = exp2f((mi[i] - mn[i]) * LOG2E);
            rsum[i] = 0.f;
#pragma unroll
            for (int j = 0; j < 4; j++) {
                s[i][j] = exp2f((s[i][j] - mn[i]) * LOG2E);
                rsum[i] += s[i][j];
            }
        }
#pragma unroll
        for (int off = 8; off; off >>= 1)
#pragma unroll
            for (int i = 0; i < 4; i++)
                rsum[i] += __shfl_xor_sync(0xffffffffu, rsum[i], off);
#pragma unroll
        for (int i = 0; i < 4; i++) {
            li[i] = li[i] * csc[i] + rsum[i];
            mi[i] = mn[i];
#pragma unroll
            for (int j = 0; j < 4; j++) O[i][j] *= csc[i];
        }

        __syncthreads();  // all K reads done before overwriting KPs with P^T

        // Store P transposed: KPs[s][row]
#pragma unroll
        for (int j = 0; j < 4; j++)
#pragma unroll
            for (int i = 0; i < 4; i++)
                KPs[(tx + 16 * j) * 65 + ty + 16 * i] = s[i][j];
        __syncthreads();

        // O += P @ V
#pragma unroll 8
        for (int kk = 0; kk < 64; kk++) {
            float a[4], b[4];
#pragma unroll
            for (int i = 0; i < 4; i++) a[i] = KPs[kk * 65 + ty + 16 * i];
#pragma unroll
            for (int j = 0; j < 4; j++) b[j] = Vs[kk * 64 + tx + 16 * j];
#pragma unroll
            for (int i = 0; i < 4; i++)
#pragma unroll
                for (int j = 0; j < 4; j++)
                    O[i][j] = fmaf(a[i], b[j], O[i][j]);
        }
    }

    // Write normalized output; channel block = head*64 (GQA reorder cancels).
#pragma unroll
    for (int i = 0; i < 4; i++) {
        float inv = 1.f / li[i];
#pragma unroll
        for (int j = 0; j < 4; j++)
            g_attn[(size_t)(m0 + ty + 16 * i) * EMB + head * HD + tx + 16 * j] =
                O[i][j] * inv;
    }
}

// =========================================================================
// LayerNorm over E=1024, one block (256 threads) per row, float4.
// =========================================================================
__global__ __launch_bounds__(256) void ln_kernel(
    const float* __restrict__ x, const float* __restrict__ gamma,
    const float* __restrict__ beta, float* __restrict__ out)
{
    const int row = blockIdx.x;
    const int tid = threadIdx.x;

    float4 v = ((const float4*)(x + (size_t)row * EMB))[tid];
    float s  = v.x + v.y + v.z + v.w;
    float ss = v.x * v.x + v.y * v.y + v.z * v.z + v.w * v.w;

    __shared__ float red1[8], red2[8];
#pragma unroll
    for (int off = 16; off; off >>= 1) {
        s  += __shfl_xor_sync(0xffffffffu, s, off);
        ss += __shfl_xor_sync(0xffffffffu, ss, off);
    }
    const int w = tid >> 5;
    if ((tid & 31) == 0) { red1[w] = s; red2[w] = ss; }
    __syncthreads();
    float ts = 0.f, tss = 0.f;
#pragma unroll
    for (int i = 0; i < 8; i++) { ts += red1[i]; tss += red2[i]; }

    const float mu   = ts * (1.f / 1024.f);
    const float var  = tss * (1.f / 1024.f) - mu * mu;
    const float rstd = rsqrtf(var + 1e-5f);

    float4 g  = ((const float4*)gamma)[tid];
    float4 bb = ((const float4*)beta)[tid];
    float4 o;
    o.x = (v.x - mu) * rstd * g.x + bb.x;
    o.y = (v.y - mu) * rstd * g.y + bb.y;
    o.z = (v.z - mu) * rstd * g.z + bb.z;
    o.w = (v.w - mu) * rstd * g.w + bb.w;
    ((float4*)(out + (size_t)row * EMB))[tid] = o;
}

// =========================================================================
extern "C" void kernel_launch(void* const* d_in, const int* in_sizes, int n_in,
                              void* d_out, int out_size)
{
    const float* query = (const float*)d_in[0];
    const float* key   = (const float*)d_in[1];
    const float* value = (const float*)d_in[2];
    const float* Wq    = (const float*)d_in[3];
    const float* bq    = (const float*)d_in[4];
    const float* Wk    = (const float*)d_in[5];
    const float* bk    = (const float*)d_in[6];
    const float* Wv    = (const float*)d_in[7];
    const float* bv    = (const float*)d_in[8];
    const float* gamma = (const float*)d_in[9];
    const float* beta  = (const float*)d_in[10];
    float* out = (float*)d_out;

    float *q, *k, *v, *attn;
    cudaGetSymbolAddress((void**)&q,    g_q);
    cudaGetSymbolAddress((void**)&k,    g_k);
    cudaGetSymbolAddress((void**)&v,    g_v);
    cudaGetSymbolAddress((void**)&attn, g_attn);

    const int ATTN_SMEM = (64 * 65 * 2 + 64 * 64) * (int)sizeof(float); // 49664
    cudaFuncSetAttribute(attn_kernel,
                         cudaFuncAttributeMaxDynamicSharedMemorySize, ATTN_SMEM);

    // Projections: q scaled by 1/sqrt(64)=0.125 (bias included in scale).
    proj_kernel<<<dim3(EMB / 64, N_SEQ / 64), 256>>>(query, Wq, bq, q, EMB, 0.125f);
    proj_kernel<<<dim3(KVE / 64, N_SEQ / 64), 256>>>(key,   Wk, bk, k, KVE, 1.0f);
    proj_kernel<<<dim3(KVE / 64, N_SEQ / 64), 256>>>(value, Wv, bv, v, KVE, 1.0f);

    // GQA attention (RoPE is identity for batch=1; see analysis).
    attn_kernel<<<dim3(N_SEQ / 64, QH), 256, ATTN_SMEM>>>();

    // LayerNorm -> final output.
    ln_kernel<<<N_SEQ, 256>>>(attn, gamma, beta, out);
}

// round 2
// speedup vs baseline: 3.1898x; 3.1898x over previous
#include <cuda_runtime.h>
#include <math.h>
#include <stdint.h>

#define N_SEQ 2048
#define EMB   1024
#define KVE   256
#define HD    64
#define QH    16

// ---------------- scratch (device globals; no allocation) ----------------
__device__ float g_q[N_SEQ * EMB];     // scaled q projection
__device__ float g_k[N_SEQ * KVE];
__device__ float g_v[N_SEQ * KVE];
__device__ float g_attn[N_SEQ * EMB];

// ---------------- helpers ----------------
__device__ __forceinline__ uint32_t f2tf32(float f) {
    uint32_t r;
    asm("cvt.rna.tf32.f32 %0, %1;" : "=r"(r) : "f"(f));
    return r;
}
__device__ __forceinline__ float ex2(float x) {
    float y;
    asm("ex2.approx.ftz.f32 %0, %1;" : "=f"(y) : "f"(x));
    return y;
}
__device__ __forceinline__ void mma_tf32(float* d,
    uint32_t a0, uint32_t a1, uint32_t a2, uint32_t a3,
    uint32_t b0, uint32_t b1)
{
    asm volatile(
        "mma.sync.aligned.m16n8k8.row.col.f32.tf32.tf32.f32 "
        "{%0,%1,%2,%3}, {%4,%5,%6,%7}, {%8,%9}, {%0,%1,%2,%3};\n"
        : "+f"(d[0]), "+f"(d[1]), "+f"(d[2]), "+f"(d[3])
        : "r"(a0), "r"(a1), "r"(a2), "r"(a3), "r"(b0), "r"(b1));
}

// =========================================================================
// tf32 projection GEMM: C[n, m] = (X[n,:] . W[m,:] + bias[m]) * scale
// 64x64 tile, BK=32, 128 threads (4 warps), warp = 16 rows x 64 cols.
// smem stride 36 (==4 mod 32) -> conflict-free fragment loads.
// =========================================================================
__global__ __launch_bounds__(128) void proj_tc(
    const float* __restrict__ X, const float* __restrict__ W,
    const float* __restrict__ bias, float* __restrict__ C,
    int M, float scale)
{
    __shared__ float Xs[64 * 36];
    __shared__ float Ws[64 * 36];

    const int tid  = threadIdx.x;
    const int lane = tid & 31;
    const int w    = tid >> 5;
    const int g    = lane >> 2;
    const int t    = lane & 3;
    const int wm   = w * 16;
    const int n0   = blockIdx.y * 64;
    const int m0   = blockIdx.x * 64;

    float acc[8][4];
#pragma unroll
    for (int nt = 0; nt < 8; nt++)
#pragma unroll
        for (int i = 0; i < 4; i++) acc[nt][i] = 0.f;

    for (int k0 = 0; k0 < EMB; k0 += 32) {
#pragma unroll
        for (int it = 0; it < 4; ++it) {
            int e = tid + it * 128;
            int r = e >> 3;            // 0..63
            int c = (e & 7) << 2;      // 0..28
            float4 xv = *(const float4*)(X + (size_t)(n0 + r) * EMB + k0 + c);
            float4 wv = *(const float4*)(W + (size_t)(m0 + r) * EMB + k0 + c);
            float* xd = Xs + r * 36 + c;
            xd[0] = xv.x; xd[1] = xv.y; xd[2] = xv.z; xd[3] = xv.w;
            float* wd = Ws + r * 36 + c;
            wd[0] = wv.x; wd[1] = wv.y; wd[2] = wv.z; wd[3] = wv.w;
        }
        __syncthreads();

#pragma unroll
        for (int kc = 0; kc < 4; kc++) {
            const float* ap = Xs + (wm + g) * 36 + kc * 8 + t;
            uint32_t a0 = f2tf32(ap[0]);
            uint32_t a1 = f2tf32(ap[8 * 36]);
            uint32_t a2 = f2tf32(ap[4]);
            uint32_t a3 = f2tf32(ap[8 * 36 + 4]);
#pragma unroll
            for (int nt = 0; nt < 8; nt++) {
                const float* bp = Ws + (nt * 8 + g) * 36 + kc * 8 + t;
                uint32_t b0 = f2tf32(bp[0]);
                uint32_t b1 = f2tf32(bp[4]);
                mma_tf32(acc[nt], a0, a1, a2, a3, b0, b1);
            }
        }
        __syncthreads();
    }

    // epilogue: C[m16n8] frag: c0/c1 row g cols 2t/2t+1; c2/c3 row g+8
#pragma unroll
    for (int nt = 0; nt < 8; nt++) {
        int col = m0 + nt * 8 + 2 * t;
        float b0 = bias[col], b1 = bias[col + 1];
        int rA = n0 + wm + g;
        int rB = rA + 8;
        C[(size_t)rA * M + col]     = (acc[nt][0] + b0) * scale;
        C[(size_t)rA * M + col + 1] = (acc[nt][1] + b1) * scale;
        C[(size_t)rB * M + col]     = (acc[nt][2] + b0) * scale;
        C[(size_t)rB * M + col + 1] = (acc[nt][3] + b1) * scale;
    }
}

// =========================================================================
// Flash GQA attention, tf32 mma. BLOCK_M=128, 8 warps, BLOCK_N=64.
// smem: Qs/Ps [128][68], Ks [64][68], Vs [64][72]  = 70656 B dynamic.
// =========================================================================
#define BM 128

__global__ __launch_bounds__(256) void attn_kernel()
{
    extern __shared__ float sm[];
    float* Qs = sm;                   // [BM][68]; reused as P after frag extract
    float* Ks = sm + BM * 68;         // [64][68]
    float* Vs = Ks + 64 * 68;         // [64][72]

    const int tid  = threadIdx.x;
    const int lane = tid & 31;
    const int w    = tid >> 5;        // 0..7
    const int g    = lane >> 2;       // 0..7
    const int t    = lane & 3;        // 0..3
    const int wm   = w * 16;
    const int head = blockIdx.y;
    const int kvh  = head >> 2;
    const int m0   = blockIdx.x * BM;

    const float* Qb = g_q + (size_t)m0 * EMB + head * HD;
    const float* Kb = g_k + kvh * HD;
    const float* Vb = g_v + kvh * HD;

    // Load Q tile (BM x 64), row-major stride 68.
#pragma unroll
    for (int it = 0; it < 8; ++it) {
        int e = tid + it * 256;
        int r = e >> 4;               // 0..127
        int c = (e & 15) << 2;
        float4 v = *(const float4*)(Qb + (size_t)r * EMB + c);
        float* d = Qs + r * 68 + c;
        d[0] = v.x; d[1] = v.y; d[2] = v.z; d[3] = v.w;
    }
    __syncthreads();

    // Extract Q fragments into registers (A-layout, 8 k-chunks).
    uint32_t qf[8][4];
#pragma unroll
    for (int kc = 0; kc < 8; kc++) {
        const float* src = Qs + (wm + g) * 68 + kc * 8 + t;
        qf[kc][0] = f2tf32(src[0]);
        qf[kc][1] = f2tf32(src[8 * 68]);
        qf[kc][2] = f2tf32(src[4]);
        qf[kc][3] = f2tf32(src[8 * 68 + 4]);
    }
    // (Qs reuse as Ps is warp-private rows; block sync at loop top covers rest.)

    float of[8][4];
#pragma unroll
    for (int nt = 0; nt < 8; nt++)
#pragma unroll
        for (int i = 0; i < 4; i++) of[nt][i] = 0.f;
    float miA = -1e30f, miB = -1e30f, liA = 0.f, liB = 0.f;

    const float LOG2E = 1.4426950408889634f;

    for (int s0 = 0; s0 < N_SEQ; s0 += 64) {
        __syncthreads();  // prior iter's Ks/Vs reads (and Q frag extract) done

        // Load K chunk -> Ks[s][d] (stride 68), V chunk -> Vs[s][d] (stride 72)
#pragma unroll
        for (int it = 0; it < 4; ++it) {
            int e = tid + it * 256;
            int r = e >> 4;           // 0..63
            int c = (e & 15) << 2;
            float4 kv = *(const float4*)(Kb + (size_t)(s0 + r) * KVE + c);
            float* kd = Ks + r * 68 + c;
            kd[0] = kv.x; kd[1] = kv.y; kd[2] = kv.z; kd[3] = kv.w;
            float4 vv = *(const float4*)(Vb + (size_t)(s0 + r) * KVE + c);
            float* vd = Vs + r * 72 + c;
            vd[0] = vv.x; vd[1] = vv.y; vd[2] = vv.z; vd[3] = vv.w;
        }
        __syncthreads();

        // ---- S = Q @ K^T (warp: 16 x 64) ----
        float sf[8][4];
#pragma unroll
        for (int nt = 0; nt < 8; nt++)
#pragma unroll
            for (int i = 0; i < 4; i++) sf[nt][i] = 0.f;

#pragma unroll
        for (int kc = 0; kc < 8; kc++) {
#pragma unroll
            for (int nt = 0; nt < 8; nt++) {
                const float* kp = Ks + (nt * 8 + g) * 68 + kc * 8 + t;
                uint32_t b0 = f2tf32(kp[0]);
                uint32_t b1 = f2tf32(kp[4]);
                mma_tf32(sf[nt], qf[kc][0], qf[kc][1], qf[kc][2], qf[kc][3],
                         b0, b1);
            }
        }

        // ---- online softmax (rows wm+g and wm+g+8) ----
        float mA = -1e30f, mB = -1e30f;
#pragma unroll
        for (int nt = 0; nt < 8; nt++) {
            mA = fmaxf(mA, fmaxf(sf[nt][0], sf[nt][1]));
            mB = fmaxf(mB, fmaxf(sf[nt][2], sf[nt][3]));
        }
        mA = fmaxf(mA, __shfl_xor_sync(0xffffffffu, mA, 1));
        mA = fmaxf(mA, __shfl_xor_sync(0xffffffffu, mA, 2));
        mB = fmaxf(mB, __shfl_xor_sync(0xffffffffu, mB, 1));
        mB = fmaxf(mB, __shfl_xor_sync(0xffffffffu, mB, 2));

        float nmA = fmaxf(miA, mA), nmB = fmaxf(miB, mB);
        float scA = ex2((miA - nmA) * LOG2E);
        float scB = ex2((miB - nmB) * LOG2E);

        float pA = 0.f, pB = 0.f;
#pragma unroll
        for (int nt = 0; nt < 8; nt++) {
            sf[nt][0] = ex2((sf[nt][0] - nmA) * LOG2E);
            sf[nt][1] = ex2((sf[nt][1] - nmA) * LOG2E);
            sf[nt][2] = ex2((sf[nt][2] - nmB) * LOG2E);
            sf[nt][3] = ex2((sf[nt][3] - nmB) * LOG2E);
            pA += sf[nt][0] + sf[nt][1];
            pB += sf[nt][2] + sf[nt][3];
        }
        pA += __shfl_xor_sync(0xffffffffu, pA, 1);
        pA += __shfl_xor_sync(0xffffffffu, pA, 2);
        pB += __shfl_xor_sync(0xffffffffu, pB, 1);
        pB += __shfl_xor_sync(0xffffffffu, pB, 2);

        liA = liA * scA + pA;  miA = nmA;
        liB = liB * scB + pB;  miB = nmB;
#pragma unroll
        for (int nt = 0; nt < 8; nt++) {
            of[nt][0] *= scA; of[nt][1] *= scA;
            of[nt][2] *= scB; of[nt][3] *= scB;
        }

        // ---- store P (warp-private rows) into Qs buffer ----
        float* Ps = Qs;
#pragma unroll
        for (int nt = 0; nt < 8; nt++) {
            *(float2*)(Ps + (wm + g) * 68 + nt * 8 + 2 * t) =
                make_float2(sf[nt][0], sf[nt][1]);
            *(float2*)(Ps + (wm + g + 8) * 68 + nt * 8 + 2 * t) =
                make_float2(sf[nt][2], sf[nt][3]);
        }
        __syncwarp();

        // ---- O += P @ V ----
#pragma unroll
        for (int kc = 0; kc < 8; kc++) {
            const float* pp = Ps + (wm + g) * 68 + kc * 8 + t;
            uint32_t a0 = f2tf32(pp[0]);
            uint32_t a1 = f2tf32(pp[8 * 68]);
            uint32_t a2 = f2tf32(pp[4]);
            uint32_t a3 = f2tf32(pp[8 * 68 + 4]);
#pragma unroll
            for (int nt = 0; nt < 8; nt++) {
                const float* vp = Vs + (kc * 8 + t) * 72 + nt * 8 + g;
                uint32_t b0 = f2tf32(vp[0]);
                uint32_t b1 = f2tf32(vp[4 * 72]);
                mma_tf32(of[nt], a0, a1, a2, a3, b0, b1);
            }
        }
        __syncwarp();   // P reads done before next-iter block sync rewrites Qs
    }

    // ---- epilogue ----
    float rA = 1.f / liA, rB = 1.f / liB;
    const int rowA = m0 + wm + g;
    const int rowB = rowA + 8;
#pragma unroll
    for (int nt = 0; nt < 8; nt++) {
        int col = head * HD + nt * 8 + 2 * t;
        *(float2*)(g_attn + (size_t)rowA * EMB + col) =
            make_float2(of[nt][0] * rA, of[nt][1] * rA);
        *(float2*)(g_attn + (size_t)rowB * EMB + col) =
            make_float2(of[nt][2] * rB, of[nt][3] * rB);
    }
}

// =========================================================================
// LayerNorm over E=1024, one block (256 threads) per row, float4.
// =========================================================================
__global__ __launch_bounds__(256) void ln_kernel(
    const float* __restrict__ x, const float* __restrict__ gamma,
    const float* __restrict__ beta, float* __restrict__ out)
{
    const int row = blockIdx.x;
    const int tid = threadIdx.x;

    float4 v = ((const float4*)(x + (size_t)row * EMB))[tid];
    float s  = v.x + v.y + v.z + v.w;
    float ss = v.x * v.x + v.y * v.y + v.z * v.z + v.w * v.w;

    __shared__ float red1[8], red2[8];
#pragma unroll
    for (int off = 16; off; off >>= 1) {
        s  += __shfl_xor_sync(0xffffffffu, s, off);
        ss += __shfl_xor_sync(0xffffffffu, ss, off);
    }
    const int w = tid >> 5;
    if ((tid & 31) == 0) { red1[w] = s; red2[w] = ss; }
    __syncthreads();
    float ts = 0.f, tss = 0.f;
#pragma unroll
    for (int i = 0; i < 8; i++) { ts += red1[i]; tss += red2[i]; }

    const float mu   = ts * (1.f / 1024.f);
    const float var  = tss * (1.f / 1024.f) - mu * mu;
    const float rstd = rsqrtf(var + 1e-5f);

    float4 gm = ((const float4*)gamma)[tid];
    float4 bb = ((const float4*)beta)[tid];
    float4 o;
    o.x = (v.x - mu) * rstd * gm.x + bb.x;
    o.y = (v.y - mu) * rstd * gm.y + bb.y;
    o.z = (v.z - mu) * rstd * gm.z + bb.z;
    o.w = (v.w - mu) * rstd * gm.w + bb.w;
    ((float4*)(out + (size_t)row * EMB))[tid] = o;
}

// =========================================================================
extern "C" void kernel_launch(void* const* d_in, const int* in_sizes, int n_in,
                              void* d_out, int out_size)
{
    const float* query = (const float*)d_in[0];
    const float* key   = (const float*)d_in[1];
    const float* value = (const float*)d_in[2];
    const float* Wq    = (const float*)d_in[3];
    const float* bq    = (const float*)d_in[4];
    const float* Wk    = (const float*)d_in[5];
    const float* bk    = (const float*)d_in[6];
    const float* Wv    = (const float*)d_in[7];
    const float* bv    = (const float*)d_in[8];
    const float* gamma = (const float*)d_in[9];
    const float* beta  = (const float*)d_in[10];
    float* out = (float*)d_out;

    float *q, *k, *v, *attn;
    cudaGetSymbolAddress((void**)&q,    g_q);
    cudaGetSymbolAddress((void**)&k,    g_k);
    cudaGetSymbolAddress((void**)&v,    g_v);
    cudaGetSymbolAddress((void**)&attn, g_attn);

    const int ATTN_SMEM = (BM * 68 + 64 * 68 + 64 * 72) * (int)sizeof(float);
    cudaFuncSetAttribute(attn_kernel,
                         cudaFuncAttributeMaxDynamicSharedMemorySize, ATTN_SMEM);

    proj_tc<<<dim3(EMB / 64, N_SEQ / 64), 128>>>(query, Wq, bq, q, EMB, 0.125f);
    proj_tc<<<dim3(KVE / 64, N_SEQ / 64), 128>>>(key,   Wk, bk, k, KVE, 1.0f);
    proj_tc<<<dim3(KVE / 64, N_SEQ / 64), 128>>>(value, Wv, bv, v, KVE, 1.0f);

    attn_kernel<<<dim3(N_SEQ / BM, QH), 256, ATTN_SMEM>>>();

    ln_kernel<<<N_SEQ, 256>>>(attn, gamma, beta, out);
}